// round 10
// baseline (speedup 1.0000x reference)
#include <cuda_runtime.h>
#include <cuda_fp16.h>
#include <cstdint>
#include <mma.h>

using namespace nvcuda;

#define FEAT 128
#define NPAD 50176
#define LDH 136   // half stride (multiple of 8), padded vs 128

// padded scratch buffers (never read beyond row n by gather)
__device__ __half g_vWn_h[NPAD * FEAT];   // v @ Wvn in fp16
__device__ float  g_Zc[NPAD * FEAT];      // v @ Wvc in fp32 (near-exact via split)
// prepped neighbor data, transposed for coalescing
__device__ uint4 g_pidx[10 * NPAD];
__device__ uint4 g_pe2[10 * NPAD];

// ---------------------------------------------------------------------------
// Kernel 1: fused split-precision HMMA GEMM.
//   Zc  = a1@w1 + a2@w1 + a1@w2   (fp16 splits, fp32 accum -> ~exact fp32)
//   vWn = a1@wn                    (fp16, fp32 accum, fp16 store)
// 128x128 CTA tile, whole K=128 in smem; 8 warps each own 32x64 of D.
// ---------------------------------------------------------------------------
__global__ __launch_bounds__(256, 2) void fused_gemm_kernel(
    const float* __restrict__ A,
    const float* __restrict__ Wvc,
    const float* __restrict__ Wvn,
    int n)
{
    extern __shared__ __half sh[];
    __half* a1 = sh;                    // [128][LDH]
    __half* a2 = sh + 128 * LDH;        // [128][LDH]
    __half* wt = sh + 2 * 128 * LDH;    // [128][LDH] (reloaded per phase)

    int tid = threadIdx.x;
    int blockRow = blockIdx.x * 128;

    // ---- load A tile -> a1 (fp16) + a2 (fp16 residual), guarded ----
    for (int i = tid; i < 128 * 32; i += 256) {
        int row = i >> 5, q = i & 31;
        int grow = blockRow + row;
        float4 v = make_float4(0.f, 0.f, 0.f, 0.f);
        if (grow < n) v = __ldg(reinterpret_cast<const float4*>(A) + grow * 32 + q);
        float f[4] = {v.x, v.y, v.z, v.w};
        __half h1[4], h2[4];
        #pragma unroll
        for (int t = 0; t < 4; t++) {
            h1[t] = __float2half_rn(f[t]);
            h2[t] = __float2half_rn(f[t] - __half2float(h1[t]));
        }
        *reinterpret_cast<uint2*>(&a1[row * LDH + q * 4]) = *reinterpret_cast<uint2*>(h1);
        *reinterpret_cast<uint2*>(&a2[row * LDH + q * 4]) = *reinterpret_cast<uint2*>(h2);
    }
    // ---- load w1 = fp16(Wvc) ----
    for (int i = tid; i < 128 * 32; i += 256) {
        int row = i >> 5, q = i & 31;
        float4 v = __ldg(reinterpret_cast<const float4*>(Wvc) + row * 32 + q);
        __half2* dst = reinterpret_cast<__half2*>(&wt[row * LDH + q * 4]);
        dst[0] = __floats2half2_rn(v.x, v.y);
        dst[1] = __floats2half2_rn(v.z, v.w);
    }
    __syncthreads();

    int w = tid >> 5;
    int m0 = (w & 3) * 32;
    int n0 = (w >> 2) * 64;

    wmma::fragment<wmma::accumulator, 16, 16, 16, float> acc[2][4];
    #pragma unroll
    for (int i = 0; i < 2; i++)
        #pragma unroll
        for (int j = 0; j < 4; j++)
            wmma::fill_fragment(acc[i][j], 0.0f);

    // ---- sweep helper (inlined twice per phase) ----
    #define SWEEP(AT)                                                          \
        _Pragma("unroll")                                                      \
        for (int k = 0; k < 128; k += 16) {                                    \
            wmma::fragment<wmma::matrix_a, 16, 16, 16, __half, wmma::row_major> fa[2]; \
            _Pragma("unroll")                                                  \
            for (int i = 0; i < 2; i++)                                        \
                wmma::load_matrix_sync(fa[i], &(AT)[(m0 + 16 * i) * LDH + k], LDH); \
            _Pragma("unroll")                                                  \
            for (int j = 0; j < 4; j++) {                                      \
                wmma::fragment<wmma::matrix_b, 16, 16, 16, __half, wmma::row_major> fb; \
                wmma::load_matrix_sync(fb, &wt[k * LDH + n0 + 16 * j], LDH);   \
                _Pragma("unroll")                                              \
                for (int i = 0; i < 2; i++)                                    \
                    wmma::mma_sync(acc[i][j], fa[i], fb, acc[i][j]);           \
            }                                                                  \
        }

    // phase 1: acc += a1@w1 + a2@w1
    SWEEP(a1)
    SWEEP(a2)
    __syncthreads();

    // phase 2: wt <- w2 = fp16(Wvc - fp16(Wvc)); acc += a1@w2
    for (int i = tid; i < 128 * 32; i += 256) {
        int row = i >> 5, q = i & 31;
        float4 v = __ldg(reinterpret_cast<const float4*>(Wvc) + row * 32 + q);
        float f[4] = {v.x, v.y, v.z, v.w};
        __half h[4];
        #pragma unroll
        for (int t = 0; t < 4; t++) {
            __half hi = __float2half_rn(f[t]);
            h[t] = __float2half_rn(f[t] - __half2float(hi));
        }
        *reinterpret_cast<uint2*>(&wt[row * LDH + q * 4]) = *reinterpret_cast<uint2*>(h);
    }
    __syncthreads();
    SWEEP(a1)

    // store Zc (fp32) to padded buffer — no guards needed
    #pragma unroll
    for (int i = 0; i < 2; i++)
        #pragma unroll
        for (int j = 0; j < 4; j++)
            wmma::store_matrix_sync(
                g_Zc + (size_t)(blockRow + m0 + 16 * i) * FEAT + n0 + 16 * j,
                acc[i][j], FEAT, wmma::mem_row_major);
    __syncthreads();

    // phase 3: wt <- fp16(Wvn); accN = a1@wn
    for (int i = tid; i < 128 * 32; i += 256) {
        int row = i >> 5, q = i & 31;
        float4 v = __ldg(reinterpret_cast<const float4*>(Wvn) + row * 32 + q);
        __half2* dst = reinterpret_cast<__half2*>(&wt[row * LDH + q * 4]);
        dst[0] = __floats2half2_rn(v.x, v.y);
        dst[1] = __floats2half2_rn(v.z, v.w);
    }
    #pragma unroll
    for (int i = 0; i < 2; i++)
        #pragma unroll
        for (int j = 0; j < 4; j++)
            wmma::fill_fragment(acc[i][j], 0.0f);
    __syncthreads();
    SWEEP(a1)

    // convert + store vWn (fp16) to padded buffer
    #pragma unroll
    for (int i = 0; i < 2; i++)
        #pragma unroll
        for (int j = 0; j < 4; j++) {
            wmma::fragment<wmma::accumulator, 16, 16, 16, __half> ch;
            #pragma unroll
            for (int t = 0; t < ch.num_elements; t++)
                ch.x[t] = __float2half(acc[i][j].x[t]);
            wmma::store_matrix_sync(
                g_vWn_h + (size_t)(blockRow + m0 + 16 * i) * FEAT + n0 + 16 * j,
                ch, FEAT, wmma::mem_row_major);
        }
    #undef SWEEP
}

// ---------------------------------------------------------------------------
// Kernel 2: prep — one thread per row; coalesced transposed output.
// ---------------------------------------------------------------------------
__global__ __launch_bounds__(256) void prep_kernel(
    const int* __restrict__ nh_idx,
    const int* __restrict__ int_idx,
    const float* __restrict__ nh_e,
    const float* __restrict__ int_e,
    int n)
{
    int row = blockIdx.x * blockDim.x + threadIdx.x;
    if (row >= n) return;

    int   idxs[40];
    float es[40];
    #pragma unroll
    for (int q = 0; q < 5; q++) {
        int4   a = __ldg(reinterpret_cast<const int4*>(nh_idx + row * 20) + q);
        float4 e = __ldg(reinterpret_cast<const float4*>(nh_e + row * 20) + q);
        idxs[4*q+0] = a.x; idxs[4*q+1] = a.y; idxs[4*q+2] = a.z; idxs[4*q+3] = a.w;
        es[4*q+0] = e.x; es[4*q+1] = e.y; es[4*q+2] = e.z; es[4*q+3] = e.w;
    }
    #pragma unroll
    for (int q = 0; q < 5; q++) {
        int4   a = __ldg(reinterpret_cast<const int4*>(int_idx + row * 20) + q);
        float4 e = __ldg(reinterpret_cast<const float4*>(int_e + row * 20) + q);
        idxs[20+4*q+0] = a.x; idxs[20+4*q+1] = a.y; idxs[20+4*q+2] = a.z; idxs[20+4*q+3] = a.w;
        es[20+4*q+0] = e.x; es[20+4*q+1] = e.y; es[20+4*q+2] = e.z; es[20+4*q+3] = e.w;
    }

    int cnt = 0;
    #pragma unroll
    for (int j = 0; j < 40; j++)
        cnt += (idxs[j] >= 0) ? 1 : 0;
    float inv = 1.0f / (float)cnt;

    #pragma unroll
    for (int q = 0; q < 10; q++) {
        uint32_t oi[4], oe[4];
        #pragma unroll
        for (int t = 0; t < 4; t++) {
            int j = 4 * q + t;
            bool v = idxs[j] >= 0;
            oi[t] = (uint32_t)(v ? idxs[j] : 0);
            __half2 h = __float2half2_rn(v ? es[j] * inv : 0.0f);
            oe[t] = *reinterpret_cast<uint32_t*>(&h);
        }
        g_pidx[q * NPAD + row] = make_uint4(oi[0], oi[1], oi[2], oi[3]);
        g_pe2[q * NPAD + row]  = make_uint4(oe[0], oe[1], oe[2], oe[3]);
    }
}

// ---------------------------------------------------------------------------
// Kernel 3: gather with HFMA2 fp16 accumulation; reads g_Zc, writes d_out.
// ---------------------------------------------------------------------------
__global__ __launch_bounds__(256, 4) void gather_kernel(
    float* __restrict__ out,
    const float* __restrict__ bv,
    int n)
{
    int gwarp = (blockIdx.x * blockDim.x + threadIdx.x) >> 5;
    int lane  = threadIdx.x & 31;
    if (gwarp >= n) return;
    int row = gwarp;

    const uint2* vW2 = reinterpret_cast<const uint2*>(g_vWn_h);

    __half2 accA0 = __float2half2_rn(0.f), accA1 = __float2half2_rn(0.f);
    __half2 accB0 = __float2half2_rn(0.f), accB1 = __float2half2_rn(0.f);

    #pragma unroll
    for (int h = 0; h < 2; h++) {
        uint32_t idxv[20], e2v[20];
        #pragma unroll
        for (int q = 0; q < 5; q++) {
            uint4 a = __ldg(&g_pidx[(h * 5 + q) * NPAD + row]);   // broadcast
            idxv[4*q+0] = a.x; idxv[4*q+1] = a.y; idxv[4*q+2] = a.z; idxv[4*q+3] = a.w;
            uint4 b = __ldg(&g_pe2[(h * 5 + q) * NPAD + row]);    // broadcast
            e2v[4*q+0] = b.x; e2v[4*q+1] = b.y; e2v[4*q+2] = b.z; e2v[4*q+3] = b.w;
        }
        #pragma unroll
        for (int j = 0; j < 20; j += 2) {
            uint2 v0 = __ldg(vW2 + (size_t)idxv[j]   * 32 + lane);
            uint2 v1 = __ldg(vW2 + (size_t)idxv[j+1] * 32 + lane);
            __half2 e0 = *reinterpret_cast<__half2*>(&e2v[j]);
            __half2 e1 = *reinterpret_cast<__half2*>(&e2v[j+1]);
            accA0 = __hfma2(*reinterpret_cast<__half2*>(&v0.x), e0, accA0);
            accB0 = __hfma2(*reinterpret_cast<__half2*>(&v0.y), e0, accB0);
            accA1 = __hfma2(*reinterpret_cast<__half2*>(&v1.x), e1, accA1);
            accB1 = __hfma2(*reinterpret_cast<__half2*>(&v1.y), e1, accB1);
        }
    }

    float2 fa = __half22float2(__hadd2(accA0, accA1));
    float2 fb = __half22float2(__hadd2(accB0, accB1));

    float4 zc = reinterpret_cast<const float4*>(g_Zc)[(size_t)row * 32 + lane];
    float4 b  = __ldg(reinterpret_cast<const float4*>(bv) + lane);
    float4 z;
    z.x = fmaxf(zc.x + fa.x + b.x, 0.f);
    z.y = fmaxf(zc.y + fa.y + b.y, 0.f);
    z.z = fmaxf(zc.z + fb.x + b.z, 0.f);
    z.w = fmaxf(zc.w + fb.y + b.w, 0.f);
    reinterpret_cast<float4*>(out)[(size_t)row * 32 + lane] = z;
}

// ---------------------------------------------------------------------------
extern "C" void kernel_launch(void* const* d_in, const int* in_sizes, int n_in,
                              void* d_out, int out_size) {
    const float* vertices    = (const float*)d_in[0];
    const int*   nh_indices  = (const int*)  d_in[1];
    const int*   int_indices = (const int*)  d_in[2];
    const float* nh_edges    = (const float*)d_in[3];
    const float* int_edges   = (const float*)d_in[4];
    const float* Wvc         = (const float*)d_in[5];
    const float* Wvn         = (const float*)d_in[6];
    const float* bv          = (const float*)d_in[7];
    float* out = (float*)d_out;

    int n = in_sizes[0] / FEAT;   // 50000
    int nblk = (n + 127) / 128;   // 391

    static const size_t gemm_smem = 3 * 128 * LDH * sizeof(__half);  // 104448
    cudaFuncSetAttribute(fused_gemm_kernel,
                         cudaFuncAttributeMaxDynamicSharedMemorySize, (int)gemm_smem);

    fused_gemm_kernel<<<nblk, 256, gemm_smem>>>(vertices, Wvc, Wvn, n);

    int gp = (n + 255) / 256;
    prep_kernel<<<gp, 256>>>(nh_indices, int_indices, nh_edges, int_edges, n);

    int g2 = (n + 7) / 8;
    gather_kernel<<<g2, 256>>>(out, bv, n);
}

// round 11
// speedup vs baseline: 1.5969x; 1.5969x over previous
#include <cuda_runtime.h>
#include <cuda_fp16.h>
#include <cstdint>
#include <mma.h>

using namespace nvcuda;

#define FEAT 128
#define NPAD 50176
#define LDH 136       // half stride (multiple of 8, LDSM conflict-free)
#define TILE_M 64

// padded scratch buffers (gather never reads beyond row n)
__device__ __half g_vWn_h[NPAD * FEAT];   // v @ Wvn in fp16
__device__ float  g_Zc[NPAD * FEAT];      // v @ Wvc in fp32 (fp16-input HMMA)
// prepped neighbor data, transposed for coalescing
__device__ uint4 g_pidx[10 * NPAD];
__device__ uint4 g_pe2[10 * NPAD];

// ---------------------------------------------------------------------------
// Kernel 1: fused HMMA GEMM, 2 logical sweeps sharing A-fragment loads.
//   Zc  = fp16(A) @ fp16(Wvc)  (fp32 accum, fp32 store)
//   vWn = fp16(A) @ fp16(Wvn)  (fp32 accum, fp16 store)
// 64x128 CTA tile; 8 warps, each 16x128-row... warp w: rows m0+16, cols n0+64.
// All tiles smem-resident; no mid-kernel W reloads.
// ---------------------------------------------------------------------------
__global__ __launch_bounds__(256, 2) void fused_gemm_kernel(
    const float* __restrict__ A,
    const float* __restrict__ Wvc,
    const float* __restrict__ Wvn,
    int n)
{
    extern __shared__ __half sh[];
    __half* a1 = sh;                        // [TILE_M][LDH]
    __half* wc = sh + TILE_M * LDH;         // [128][LDH]
    __half* wn = sh + (TILE_M + 128) * LDH; // [128][LDH]

    int tid = threadIdx.x;
    int blockRow = blockIdx.x * TILE_M;

    // ---- load A tile (guarded) ----
    #pragma unroll
    for (int i = tid; i < TILE_M * 32; i += 256) {
        int row = i >> 5, q = i & 31;
        int grow = blockRow + row;
        float4 v = make_float4(0.f, 0.f, 0.f, 0.f);
        if (grow < n) v = __ldg(reinterpret_cast<const float4*>(A) + grow * 32 + q);
        __half2* dst = reinterpret_cast<__half2*>(&a1[row * LDH + q * 4]);
        dst[0] = __floats2half2_rn(v.x, v.y);
        dst[1] = __floats2half2_rn(v.z, v.w);
    }
    // ---- load both W tiles (unguarded) ----
    #pragma unroll
    for (int i = tid; i < 128 * 32; i += 256) {
        int row = i >> 5, q = i & 31;
        float4 v = __ldg(reinterpret_cast<const float4*>(Wvc) + row * 32 + q);
        __half2* dst = reinterpret_cast<__half2*>(&wc[row * LDH + q * 4]);
        dst[0] = __floats2half2_rn(v.x, v.y);
        dst[1] = __floats2half2_rn(v.z, v.w);
    }
    #pragma unroll
    for (int i = tid; i < 128 * 32; i += 256) {
        int row = i >> 5, q = i & 31;
        float4 v = __ldg(reinterpret_cast<const float4*>(Wvn) + row * 32 + q);
        __half2* dst = reinterpret_cast<__half2*>(&wn[row * LDH + q * 4]);
        dst[0] = __floats2half2_rn(v.x, v.y);
        dst[1] = __floats2half2_rn(v.z, v.w);
    }
    __syncthreads();

    int w = tid >> 5;
    int m0 = (w & 3) * 16;      // 4 row groups of 16
    int n0 = (w >> 2) * 64;     // 2 col groups of 64

    wmma::fragment<wmma::accumulator, 16, 16, 16, float> accC[4], accN[4];
    #pragma unroll
    for (int j = 0; j < 4; j++) {
        wmma::fill_fragment(accC[j], 0.0f);
        wmma::fill_fragment(accN[j], 0.0f);
    }

    #pragma unroll
    for (int k = 0; k < 128; k += 16) {
        wmma::fragment<wmma::matrix_a, 16, 16, 16, __half, wmma::row_major> fa;
        wmma::load_matrix_sync(fa, &a1[m0 * LDH + k], LDH);
        #pragma unroll
        for (int j = 0; j < 4; j++) {
            wmma::fragment<wmma::matrix_b, 16, 16, 16, __half, wmma::row_major> fbC, fbN;
            wmma::load_matrix_sync(fbC, &wc[k * LDH + n0 + 16 * j], LDH);
            wmma::mma_sync(accC[j], fa, fbC, accC[j]);
            wmma::load_matrix_sync(fbN, &wn[k * LDH + n0 + 16 * j], LDH);
            wmma::mma_sync(accN[j], fa, fbN, accN[j]);
        }
    }

    // ---- stores (padded buffers, no guards) ----
    #pragma unroll
    for (int j = 0; j < 4; j++)
        wmma::store_matrix_sync(
            g_Zc + (size_t)(blockRow + m0) * FEAT + n0 + 16 * j,
            accC[j], FEAT, wmma::mem_row_major);
    #pragma unroll
    for (int j = 0; j < 4; j++) {
        wmma::fragment<wmma::accumulator, 16, 16, 16, __half> ch;
        #pragma unroll
        for (int t = 0; t < ch.num_elements; t++)
            ch.x[t] = __float2half(accN[j].x[t]);
        wmma::store_matrix_sync(
            g_vWn_h + (size_t)(blockRow + m0) * FEAT + n0 + 16 * j,
            ch, FEAT, wmma::mem_row_major);
    }
}

// ---------------------------------------------------------------------------
// Kernel 2: prep — one thread per row; coalesced transposed output.
// ---------------------------------------------------------------------------
__global__ __launch_bounds__(256) void prep_kernel(
    const int* __restrict__ nh_idx,
    const int* __restrict__ int_idx,
    const float* __restrict__ nh_e,
    const float* __restrict__ int_e,
    int n)
{
    int row = blockIdx.x * blockDim.x + threadIdx.x;
    if (row >= n) return;

    int   idxs[40];
    float es[40];
    #pragma unroll
    for (int q = 0; q < 5; q++) {
        int4   a = __ldg(reinterpret_cast<const int4*>(nh_idx + row * 20) + q);
        float4 e = __ldg(reinterpret_cast<const float4*>(nh_e + row * 20) + q);
        idxs[4*q+0] = a.x; idxs[4*q+1] = a.y; idxs[4*q+2] = a.z; idxs[4*q+3] = a.w;
        es[4*q+0] = e.x; es[4*q+1] = e.y; es[4*q+2] = e.z; es[4*q+3] = e.w;
    }
    #pragma unroll
    for (int q = 0; q < 5; q++) {
        int4   a = __ldg(reinterpret_cast<const int4*>(int_idx + row * 20) + q);
        float4 e = __ldg(reinterpret_cast<const float4*>(int_e + row * 20) + q);
        idxs[20+4*q+0] = a.x; idxs[20+4*q+1] = a.y; idxs[20+4*q+2] = a.z; idxs[20+4*q+3] = a.w;
        es[20+4*q+0] = e.x; es[20+4*q+1] = e.y; es[20+4*q+2] = e.z; es[20+4*q+3] = e.w;
    }

    int cnt = 0;
    #pragma unroll
    for (int j = 0; j < 40; j++)
        cnt += (idxs[j] >= 0) ? 1 : 0;
    float inv = 1.0f / (float)cnt;

    #pragma unroll
    for (int q = 0; q < 10; q++) {
        uint32_t oi[4], oe[4];
        #pragma unroll
        for (int t = 0; t < 4; t++) {
            int j = 4 * q + t;
            bool v = idxs[j] >= 0;
            oi[t] = (uint32_t)(v ? idxs[j] : 0);
            __half2 h = __float2half2_rn(v ? es[j] * inv : 0.0f);
            oe[t] = *reinterpret_cast<uint32_t*>(&h);
        }
        g_pidx[q * NPAD + row] = make_uint4(oi[0], oi[1], oi[2], oi[3]);
        g_pe2[q * NPAD + row]  = make_uint4(oe[0], oe[1], oe[2], oe[3]);
    }
}

// ---------------------------------------------------------------------------
// Kernel 3: gather with HFMA2 fp16 accumulation; reads g_Zc, writes d_out.
// ---------------------------------------------------------------------------
__global__ __launch_bounds__(256, 4) void gather_kernel(
    float* __restrict__ out,
    const float* __restrict__ bv,
    int n)
{
    int gwarp = (blockIdx.x * blockDim.x + threadIdx.x) >> 5;
    int lane  = threadIdx.x & 31;
    if (gwarp >= n) return;
    int row = gwarp;

    const uint2* vW2 = reinterpret_cast<const uint2*>(g_vWn_h);

    __half2 accA0 = __float2half2_rn(0.f), accA1 = __float2half2_rn(0.f);
    __half2 accB0 = __float2half2_rn(0.f), accB1 = __float2half2_rn(0.f);

    #pragma unroll
    for (int h = 0; h < 2; h++) {
        uint32_t idxv[20], e2v[20];
        #pragma unroll
        for (int q = 0; q < 5; q++) {
            uint4 a = __ldg(&g_pidx[(h * 5 + q) * NPAD + row]);   // broadcast
            idxv[4*q+0] = a.x; idxv[4*q+1] = a.y; idxv[4*q+2] = a.z; idxv[4*q+3] = a.w;
            uint4 b = __ldg(&g_pe2[(h * 5 + q) * NPAD + row]);    // broadcast
            e2v[4*q+0] = b.x; e2v[4*q+1] = b.y; e2v[4*q+2] = b.z; e2v[4*q+3] = b.w;
        }
        #pragma unroll
        for (int j = 0; j < 20; j += 2) {
            uint2 v0 = __ldg(vW2 + (size_t)idxv[j]   * 32 + lane);
            uint2 v1 = __ldg(vW2 + (size_t)idxv[j+1] * 32 + lane);
            __half2 e0 = *reinterpret_cast<__half2*>(&e2v[j]);
            __half2 e1 = *reinterpret_cast<__half2*>(&e2v[j+1]);
            accA0 = __hfma2(*reinterpret_cast<__half2*>(&v0.x), e0, accA0);
            accB0 = __hfma2(*reinterpret_cast<__half2*>(&v0.y), e0, accB0);
            accA1 = __hfma2(*reinterpret_cast<__half2*>(&v1.x), e1, accA1);
            accB1 = __hfma2(*reinterpret_cast<__half2*>(&v1.y), e1, accB1);
        }
    }

    float2 fa = __half22float2(__hadd2(accA0, accA1));
    float2 fb = __half22float2(__hadd2(accB0, accB1));

    float4 zc = reinterpret_cast<const float4*>(g_Zc)[(size_t)row * 32 + lane];
    float4 b  = __ldg(reinterpret_cast<const float4*>(bv) + lane);
    float4 z;
    z.x = fmaxf(zc.x + fa.x + b.x, 0.f);
    z.y = fmaxf(zc.y + fa.y + b.y, 0.f);
    z.z = fmaxf(zc.z + fb.x + b.z, 0.f);
    z.w = fmaxf(zc.w + fb.y + b.w, 0.f);
    reinterpret_cast<float4*>(out)[(size_t)row * 32 + lane] = z;
}

// ---------------------------------------------------------------------------
extern "C" void kernel_launch(void* const* d_in, const int* in_sizes, int n_in,
                              void* d_out, int out_size) {
    const float* vertices    = (const float*)d_in[0];
    const int*   nh_indices  = (const int*)  d_in[1];
    const int*   int_indices = (const int*)  d_in[2];
    const float* nh_edges    = (const float*)d_in[3];
    const float* int_edges   = (const float*)d_in[4];
    const float* Wvc         = (const float*)d_in[5];
    const float* Wvn         = (const float*)d_in[6];
    const float* bv          = (const float*)d_in[7];
    float* out = (float*)d_out;

    int n = in_sizes[0] / FEAT;   // 50000
    int nblk = (n + TILE_M - 1) / TILE_M;   // 782

    static const size_t gemm_smem = (size_t)(TILE_M + 256) * LDH * sizeof(__half); // 87040
    cudaFuncSetAttribute(fused_gemm_kernel,
                         cudaFuncAttributeMaxDynamicSharedMemorySize, (int)gemm_smem);

    fused_gemm_kernel<<<nblk, 256, gemm_smem>>>(vertices, Wvc, Wvn, n);

    int gp = (n + 255) / 256;
    prep_kernel<<<gp, 256>>>(nh_indices, int_indices, nh_edges, int_edges, n);

    int g2 = (n + 7) / 8;
    gather_kernel<<<g2, 256>>>(out, bv, n);
}

// round 12
// speedup vs baseline: 1.7515x; 1.0968x over previous
#include <cuda_runtime.h>
#include <cuda_fp16.h>
#include <cstdint>
#include <mma.h>

using namespace nvcuda;

#define FEAT 128
#define NPAD 50176
#define LDH 136       // half stride (multiple of 8, LDSM conflict-free)
#define TILE_M 64

// padded scratch buffers (gather never reads beyond row n)
__device__ __half g_vWn_h[NPAD * FEAT];   // v @ Wvn in fp16
__device__ float  g_Zc[NPAD * FEAT];      // v @ Wvc in fp32
// prepped neighbor data, transposed for coalescing
__device__ uint4 g_pidx[10 * NPAD];
__device__ uint4 g_pe2[10 * NPAD];

// ---------------------------------------------------------------------------
// Kernel 1: fused HMMA GEMM (2 sweeps sharing A fragments) + prep CTAs.
//   blockIdx.x <  nblk : 64x128 GEMM tile -> g_Zc (fp32), g_vWn_h (fp16)
//   blockIdx.x >= nblk : neighbor prep (one thread per row, coalesced output)
// ---------------------------------------------------------------------------
__global__ __launch_bounds__(256, 2) void fused_gemm_prep_kernel(
    const float* __restrict__ A,
    const float* __restrict__ Wvc,
    const float* __restrict__ Wvn,
    const int* __restrict__ nh_idx,
    const int* __restrict__ int_idx,
    const float* __restrict__ nh_e,
    const float* __restrict__ int_e,
    int n, int nblk)
{
    int tid = threadIdx.x;

    if ((int)blockIdx.x >= nblk) {
        // ------------------------- prep path ------------------------------
        int row = (blockIdx.x - nblk) * 256 + tid;
        if (row >= n) return;

        int   idxs[40];
        float es[40];
        #pragma unroll
        for (int q = 0; q < 5; q++) {
            int4   a = __ldg(reinterpret_cast<const int4*>(nh_idx + row * 20) + q);
            float4 e = __ldg(reinterpret_cast<const float4*>(nh_e + row * 20) + q);
            idxs[4*q+0] = a.x; idxs[4*q+1] = a.y; idxs[4*q+2] = a.z; idxs[4*q+3] = a.w;
            es[4*q+0] = e.x; es[4*q+1] = e.y; es[4*q+2] = e.z; es[4*q+3] = e.w;
        }
        #pragma unroll
        for (int q = 0; q < 5; q++) {
            int4   a = __ldg(reinterpret_cast<const int4*>(int_idx + row * 20) + q);
            float4 e = __ldg(reinterpret_cast<const float4*>(int_e + row * 20) + q);
            idxs[20+4*q+0] = a.x; idxs[20+4*q+1] = a.y; idxs[20+4*q+2] = a.z; idxs[20+4*q+3] = a.w;
            es[20+4*q+0] = e.x; es[20+4*q+1] = e.y; es[20+4*q+2] = e.z; es[20+4*q+3] = e.w;
        }

        int cnt = 0;
        #pragma unroll
        for (int j = 0; j < 40; j++)
            cnt += (idxs[j] >= 0) ? 1 : 0;
        float inv = 1.0f / (float)cnt;

        #pragma unroll
        for (int q = 0; q < 10; q++) {
            uint32_t oi[4], oe[4];
            #pragma unroll
            for (int t = 0; t < 4; t++) {
                int j = 4 * q + t;
                bool v = idxs[j] >= 0;
                oi[t] = (uint32_t)(v ? idxs[j] : 0);
                __half2 h = __float2half2_rn(v ? es[j] * inv : 0.0f);
                oe[t] = *reinterpret_cast<uint32_t*>(&h);
            }
            g_pidx[q * NPAD + row] = make_uint4(oi[0], oi[1], oi[2], oi[3]);
            g_pe2[q * NPAD + row]  = make_uint4(oe[0], oe[1], oe[2], oe[3]);
        }
        return;
    }

    // --------------------------- GEMM path --------------------------------
    extern __shared__ __half sh[];
    __half* a1 = sh;                        // [TILE_M][LDH]
    __half* wc = sh + TILE_M * LDH;         // [128][LDH]
    __half* wn = sh + (TILE_M + 128) * LDH; // [128][LDH]

    int blockRow = blockIdx.x * TILE_M;

    #pragma unroll
    for (int i = tid; i < TILE_M * 32; i += 256) {
        int row = i >> 5, q = i & 31;
        int grow = blockRow + row;
        float4 v = make_float4(0.f, 0.f, 0.f, 0.f);
        if (grow < n) v = __ldg(reinterpret_cast<const float4*>(A) + grow * 32 + q);
        __half2* dst = reinterpret_cast<__half2*>(&a1[row * LDH + q * 4]);
        dst[0] = __floats2half2_rn(v.x, v.y);
        dst[1] = __floats2half2_rn(v.z, v.w);
    }
    #pragma unroll
    for (int i = tid; i < 128 * 32; i += 256) {
        int row = i >> 5, q = i & 31;
        float4 v = __ldg(reinterpret_cast<const float4*>(Wvc) + row * 32 + q);
        __half2* dst = reinterpret_cast<__half2*>(&wc[row * LDH + q * 4]);
        dst[0] = __floats2half2_rn(v.x, v.y);
        dst[1] = __floats2half2_rn(v.z, v.w);
    }
    #pragma unroll
    for (int i = tid; i < 128 * 32; i += 256) {
        int row = i >> 5, q = i & 31;
        float4 v = __ldg(reinterpret_cast<const float4*>(Wvn) + row * 32 + q);
        __half2* dst = reinterpret_cast<__half2*>(&wn[row * LDH + q * 4]);
        dst[0] = __floats2half2_rn(v.x, v.y);
        dst[1] = __floats2half2_rn(v.z, v.w);
    }
    __syncthreads();

    int w = tid >> 5;
    int m0 = (w & 3) * 16;
    int n0 = (w >> 2) * 64;

    wmma::fragment<wmma::accumulator, 16, 16, 16, float> accC[4], accN[4];
    #pragma unroll
    for (int j = 0; j < 4; j++) {
        wmma::fill_fragment(accC[j], 0.0f);
        wmma::fill_fragment(accN[j], 0.0f);
    }

    #pragma unroll
    for (int k = 0; k < 128; k += 16) {
        wmma::fragment<wmma::matrix_a, 16, 16, 16, __half, wmma::row_major> fa;
        wmma::load_matrix_sync(fa, &a1[m0 * LDH + k], LDH);
        #pragma unroll
        for (int j = 0; j < 4; j++) {
            wmma::fragment<wmma::matrix_b, 16, 16, 16, __half, wmma::row_major> fbC, fbN;
            wmma::load_matrix_sync(fbC, &wc[k * LDH + n0 + 16 * j], LDH);
            wmma::mma_sync(accC[j], fa, fbC, accC[j]);
            wmma::load_matrix_sync(fbN, &wn[k * LDH + n0 + 16 * j], LDH);
            wmma::mma_sync(accN[j], fa, fbN, accN[j]);
        }
    }

    #pragma unroll
    for (int j = 0; j < 4; j++)
        wmma::store_matrix_sync(
            g_Zc + (size_t)(blockRow + m0) * FEAT + n0 + 16 * j,
            accC[j], FEAT, wmma::mem_row_major);
    #pragma unroll
    for (int j = 0; j < 4; j++) {
        wmma::fragment<wmma::accumulator, 16, 16, 16, __half> ch;
        #pragma unroll
        for (int t = 0; t < ch.num_elements; t++)
            ch.x[t] = __float2half(accN[j].x[t]);
        wmma::store_matrix_sync(
            g_vWn_h + (size_t)(blockRow + m0) * FEAT + n0 + 16 * j,
            ch, FEAT, wmma::mem_row_major);
    }
}

// ---------------------------------------------------------------------------
// Kernel 2: gather v2 — two rows per warp (half-warps), LDG.128 gathers.
// sub-lane owns 16 bytes = 8 halves = cols [sub*8, sub*8+8).
// Per q-group: 2 broadcast loads + 4 x LDG.128 + 16 HFMA2 (two chains).
// ---------------------------------------------------------------------------
__global__ __launch_bounds__(256, 5) void gather_kernel(
    float* __restrict__ out,
    const float* __restrict__ bv,
    int n)
{
    int warp = (blockIdx.x * blockDim.x + threadIdx.x) >> 5;
    int lane = threadIdx.x & 31;
    int half = lane >> 4;     // 0/1 -> which row
    int sub  = lane & 15;     // 16B chunk within the row
    int row  = warp * 2 + half;
    if (row >= n) return;

    const uint4* vW16 = reinterpret_cast<const uint4*>(g_vWn_h);  // 16 uint4/row

    __half2 accA[4], accB[4];
    #pragma unroll
    for (int c = 0; c < 4; c++) {
        accA[c] = __float2half2_rn(0.f);
        accB[c] = __float2half2_rn(0.f);
    }

    #pragma unroll
    for (int q = 0; q < 10; q++) {
        uint4 a = __ldg(&g_pidx[q * NPAD + row]);   // broadcast per half-warp
        uint4 e = __ldg(&g_pe2[q * NPAD + row]);
        uint4 v0 = __ldg(vW16 + (size_t)a.x * 16 + sub);
        uint4 v1 = __ldg(vW16 + (size_t)a.y * 16 + sub);
        uint4 v2 = __ldg(vW16 + (size_t)a.z * 16 + sub);
        uint4 v3 = __ldg(vW16 + (size_t)a.w * 16 + sub);
        __half2 e0 = *reinterpret_cast<__half2*>(&e.x);
        __half2 e1 = *reinterpret_cast<__half2*>(&e.y);
        __half2 e2 = *reinterpret_cast<__half2*>(&e.z);
        __half2 e3 = *reinterpret_cast<__half2*>(&e.w);
        const uint32_t* p0 = &v0.x;
        const uint32_t* p1 = &v1.x;
        const uint32_t* p2 = &v2.x;
        const uint32_t* p3 = &v3.x;
        #pragma unroll
        for (int c = 0; c < 4; c++) {
            accA[c] = __hfma2(*reinterpret_cast<const __half2*>(p0 + c), e0, accA[c]);
            accB[c] = __hfma2(*reinterpret_cast<const __half2*>(p1 + c), e1, accB[c]);
            accA[c] = __hfma2(*reinterpret_cast<const __half2*>(p2 + c), e2, accA[c]);
            accB[c] = __hfma2(*reinterpret_cast<const __half2*>(p3 + c), e3, accB[c]);
        }
    }

    float2 f[4];
    #pragma unroll
    for (int c = 0; c < 4; c++)
        f[c] = __half22float2(__hadd2(accA[c], accB[c]));

    const float4* zc4 = reinterpret_cast<const float4*>(g_Zc) + (size_t)row * 32 + sub * 2;
    const float4* bv4 = reinterpret_cast<const float4*>(bv) + sub * 2;
    float4 zc0 = zc4[0], zc1 = zc4[1];
    float4 b0 = __ldg(bv4), b1 = __ldg(bv4 + 1);
    float4 z0, z1;
    z0.x = fmaxf(zc0.x + f[0].x + b0.x, 0.f);
    z0.y = fmaxf(zc0.y + f[0].y + b0.y, 0.f);
    z0.z = fmaxf(zc0.z + f[1].x + b0.z, 0.f);
    z0.w = fmaxf(zc0.w + f[1].y + b0.w, 0.f);
    z1.x = fmaxf(zc1.x + f[2].x + b1.x, 0.f);
    z1.y = fmaxf(zc1.y + f[2].y + b1.y, 0.f);
    z1.z = fmaxf(zc1.z + f[3].x + b1.z, 0.f);
    z1.w = fmaxf(zc1.w + f[3].y + b1.w, 0.f);
    float4* o4 = reinterpret_cast<float4*>(out) + (size_t)row * 32 + sub * 2;
    o4[0] = z0;
    o4[1] = z1;
}

// ---------------------------------------------------------------------------
extern "C" void kernel_launch(void* const* d_in, const int* in_sizes, int n_in,
                              void* d_out, int out_size) {
    const float* vertices    = (const float*)d_in[0];
    const int*   nh_indices  = (const int*)  d_in[1];
    const int*   int_indices = (const int*)  d_in[2];
    const float* nh_edges    = (const float*)d_in[3];
    const float* int_edges   = (const float*)d_in[4];
    const float* Wvc         = (const float*)d_in[5];
    const float* Wvn         = (const float*)d_in[6];
    const float* bv          = (const float*)d_in[7];
    float* out = (float*)d_out;

    int n = in_sizes[0] / FEAT;             // 50000
    int nblk = (n + TILE_M - 1) / TILE_M;   // 782
    int pblk = (n + 255) / 256;             // 196

    static const size_t gemm_smem = (size_t)(TILE_M + 256) * LDH * sizeof(__half); // 87040
    cudaFuncSetAttribute(fused_gemm_prep_kernel,
                         cudaFuncAttributeMaxDynamicSharedMemorySize, (int)gemm_smem);

    fused_gemm_prep_kernel<<<nblk + pblk, 256, gemm_smem>>>(
        vertices, Wvc, Wvn, nh_indices, int_indices, nh_edges, int_edges, n, nblk);

    int nwarp = (n + 1) / 2;                 // 2 rows per warp
    int g2 = (nwarp + 7) / 8;                // 8 warps per block
    gather_kernel<<<g2, 256>>>(out, bv, n);
}